// round 15
// baseline (speedup 1.0000x reference)
#include <cuda_runtime.h>
#include <cuda_fp16.h>
#include <math.h>
#include <stdint.h>

#define N_NODES  100000
#define N_EDGES  1600000
#define N_GRAPHS 1000
#define D        128
#define NBLK     98            // ceil(N_NODES / 1024)

// ---------------- scratch (static device globals; no allocation) ----------------
__device__ __half   g_hh   [(size_t)N_NODES * D];  // current activations (fp16)
__device__ __half   g_hsh  [(size_t)N_NODES * D];  // (h @ W) * dinv[row] in fp16
__device__ uint32_t g_Wt   [3 * D * D];            // weights as TF32 bit patterns [l][k][n]
__device__ float    g_dinv [N_NODES];
__device__ int      g_deg  [N_NODES];
__device__ int      g_rowptr[N_NODES + 1];
__device__ int      g_cursor[N_NODES];
__device__ int      g_esrc [N_EDGES];              // src ids sorted by dst (CSR)
__device__ int      g_bsum [NBLK];
__device__ int      g_bsumx[NBLK];
__device__ float    g_gmax [N_GRAPHS * D];

// ---------------- degree count ----------------
__global__ void k_count_deg(const int* __restrict__ dst) {
    int e = blockIdx.x * blockDim.x + threadIdx.x;
    if (e < N_EDGES) atomicAdd(&g_deg[dst[e]], 1);
}

// ---------------- coalesced CSR prefix: 3 kernels ----------------
__global__ __launch_bounds__(1024) void k_blocksum() {
    int tid = threadIdx.x;
    int i   = blockIdx.x * 1024 + tid;
    int dg  = (i < N_NODES) ? g_deg[i] : 0;
    int x = dg;
    #pragma unroll
    for (int o = 16; o; o >>= 1) x += __shfl_xor_sync(0xFFFFFFFFu, x, o);
    __shared__ int wsum[32];
    if ((tid & 31) == 0) wsum[tid >> 5] = x;
    __syncthreads();
    if (tid < 32) {
        int v = wsum[tid];
        #pragma unroll
        for (int o = 16; o; o >>= 1) v += __shfl_xor_sync(0xFFFFFFFFu, v, o);
        if (tid == 0) g_bsum[blockIdx.x] = v;
    }
}

__global__ void k_scan_part() {
    __shared__ int s[128];
    int t = threadIdx.x;
    s[t] = (t < NBLK) ? g_bsum[t] : 0;
    __syncthreads();
    for (int off = 1; off < 128; off <<= 1) {
        int v = (t >= off) ? s[t - off] : 0;
        __syncthreads();
        s[t] += v;
        __syncthreads();
    }
    if (t < NBLK) g_bsumx[t] = s[t] - g_bsum[t];   // exclusive
}

__global__ __launch_bounds__(1024) void k_write_csr() {
    int tid  = threadIdx.x;
    int lane = tid & 31;
    int wid  = tid >> 5;
    int i    = blockIdx.x * 1024 + tid;
    int dg   = (i < N_NODES) ? g_deg[i] : 0;

    int x = dg;
    #pragma unroll
    for (int o = 1; o < 32; o <<= 1) {
        int y = __shfl_up_sync(0xFFFFFFFFu, x, o);
        if (lane >= o) x += y;
    }
    __shared__ int wsum[32];
    if (lane == 31) wsum[wid] = x;
    __syncthreads();
    if (tid < 32) {
        int v = wsum[tid];
        #pragma unroll
        for (int o = 1; o < 32; o <<= 1) {
            int y = __shfl_up_sync(0xFFFFFFFFu, v, o);
            if (tid >= o) v += y;
        }
        wsum[tid] = v;
    }
    __syncthreads();

    if (i < N_NODES) {
        int base = g_bsumx[blockIdx.x] + ((wid > 0) ? wsum[wid - 1] : 0);
        int excl = base + x - dg;
        g_rowptr[i] = excl;
        g_cursor[i] = excl;
        g_dinv[i]   = rsqrtf((float)dg + 1.0f);
    }
    if (i == 0) g_rowptr[N_NODES] = N_EDGES;
}

// ---------------- CSR fill ----------------
__global__ void k_fill_csr(const int* __restrict__ src, const int* __restrict__ dst) {
    int e = blockIdx.x * blockDim.x + threadIdx.x;
    if (e >= N_EDGES) return;
    int d   = __ldg(dst + e);
    int pos = atomicAdd(&g_cursor[d], 1);
    g_esrc[pos] = __ldg(src + e);
}

// ---------------- TF32 helpers ----------------
__device__ __forceinline__ uint32_t f2tf32(float x) {
    uint32_t r;
    asm("cvt.rna.tf32.f32 %0, %1;" : "=r"(r) : "f"(x));
    return r;
}
__device__ __forceinline__ uint2 h2_to_tf32(uint32_t h2raw) {
    float2 f = __half22float2(*(__half2*)&h2raw);
    return make_uint2(f2tf32(f.x), f2tf32(f.y));
}
__device__ __forceinline__ void mma_tf32(float* c, const uint32_t a0, const uint32_t a1,
                                         const uint32_t a2, const uint32_t a3,
                                         const uint32_t b0, const uint32_t b1) {
    asm volatile(
        "mma.sync.aligned.m16n8k8.row.col.f32.tf32.tf32.f32 "
        "{%0,%1,%2,%3}, {%4,%5,%6,%7}, {%8,%9}, {%0,%1,%2,%3};"
        : "+f"(c[0]), "+f"(c[1]), "+f"(c[2]), "+f"(c[3])
        : "r"(a0), "r"(a1), "r"(a2), "r"(a3), "r"(b0), "r"(b1));
}

// ---------------- weights -> TF32 bit patterns (same [k][n] layout) ----------------
__global__ void k_prepW(const float* __restrict__ W0, const float* __restrict__ W1,
                        const float* __restrict__ W2) {
    int idx = blockIdx.x * blockDim.x + threadIdx.x;
    if (idx >= 3 * D * D) return;
    int l   = idx >> 14;               // D*D = 16384
    int rem = idx & (D * D - 1);
    const float* W = (l == 0) ? W0 : (l == 1) ? W1 : W2;
    g_Wt[idx] = f2tf32(W[rem]);
}

// ---------------- embedding lookup with max_norm=1 renorm -> fp16 ----------------
__global__ void k_embed(const int* __restrict__ x, const float* __restrict__ emb) {
    int t    = blockIdx.x * blockDim.x + threadIdx.x;
    int node = t >> 5;
    int lane = t & 31;
    if (node >= N_NODES) return;
    int v = __ldg(x + node);
    float4 e = __ldg((const float4*)(emb + (size_t)v * D) + lane);
    float ss = e.x * e.x + e.y * e.y + e.z * e.z + e.w * e.w;
    #pragma unroll
    for (int o = 16; o; o >>= 1) ss += __shfl_xor_sync(0xFFFFFFFFu, ss, o);
    float nrm   = sqrtf(ss);
    float scale = fminf(1.0f, 1.0f / fmaxf(nrm, 1e-7f));
    __half2 h0 = __float22half2_rn(make_float2(e.x * scale, e.y * scale));
    __half2 h1 = __float22half2_rn(make_float2(e.z * scale, e.w * scale));
    uint2 outv;
    outv.x = *(uint32_t*)&h0;
    outv.y = *(uint32_t*)&h1;
    ((uint2*)(g_hh + (size_t)node * D))[lane] = outv;
}

// ---------------- GEMM (single TF32, fp16 A input, pre-converted W, reg prefetch) -----
// hs_h = fp16((fp32(g_hh) @ W) * dinv[row])
// Block 128x128, 8 warps 4(M)x2(N), warp tile 32x64, mma m16n8k8, K chunks of 32.
#define A_STRIDE 36
#define B_STRIDE 136
__global__ __launch_bounds__(256) void k_gemm(int layer) {
    __shared__ uint32_t As[128][A_STRIDE];
    __shared__ uint32_t Bs[32][B_STRIDE];

    const uint32_t* Wt = g_Wt + (layer << 14);

    int tid  = threadIdx.x;
    int warp = tid >> 5, lane = tid & 31;
    int g = lane >> 2, t = lane & 3;
    int wm = warp >> 1;            // 0..3
    int wn = warp & 1;             // 0..1
    int rowBase = blockIdx.x * 128;
    int mBase = wm * 32;
    int nBase = wn * 64;

    float acc[2][8][4];
    #pragma unroll
    for (int i = 0; i < 2; i++)
        #pragma unroll
        for (int j = 0; j < 8; j++)
            #pragma unroll
            for (int k = 0; k < 4; k++) acc[i][j][k] = 0.0f;

    // staging coords
    const int ar  = tid >> 1;              // A row (2 threads per row)
    const int ac  = (tid & 1) << 4;        // A col base: 0 or 16 (16 halves)
    const int agr = rowBase + ar;
    const bool aok = agr < N_NODES;

    uint4 aRaw[2];                         // 16 halves
    uint4 bReg[4];                         // pre-converted TF32 bits

    // prefetch chunk 0
    {
        const __half* ap = g_hh + (size_t)agr * D + ac;
        aRaw[0] = aok ? *(const uint4*)(ap)     : make_uint4(0,0,0,0);
        aRaw[1] = aok ? *(const uint4*)(ap + 8) : make_uint4(0,0,0,0);
        #pragma unroll
        for (int i = 0; i < 4; i++) {
            int idx = tid + i * 256;
            int r   = idx >> 5;
            int c   = (idx & 31) << 2;
            bReg[i] = __ldg((const uint4*)(Wt + (size_t)r * D + c));
        }
    }

    for (int kc = 0; kc < 4; kc++) {
        // cvt A + copy B to smem
        #pragma unroll
        for (int h = 0; h < 2; h++) {
            uint2 p0 = h2_to_tf32(aRaw[h].x);
            uint2 p1 = h2_to_tf32(aRaw[h].y);
            uint2 p2 = h2_to_tf32(aRaw[h].z);
            uint2 p3 = h2_to_tf32(aRaw[h].w);
            int off = ac + h * 8;
            *(uint4*)&As[ar][off]     = make_uint4(p0.x, p0.y, p1.x, p1.y);
            *(uint4*)&As[ar][off + 4] = make_uint4(p2.x, p2.y, p3.x, p3.y);
        }
        #pragma unroll
        for (int i = 0; i < 4; i++) {
            int idx = tid + i * 256;
            int r   = idx >> 5;
            int c   = (idx & 31) << 2;
            *(uint4*)&Bs[r][c] = bReg[i];
        }
        __syncthreads();

        // prefetch next chunk while MMAs run
        if (kc < 3) {
            int k0 = (kc + 1) * 32;
            const __half* ap = g_hh + (size_t)agr * D + k0 + ac;
            aRaw[0] = aok ? *(const uint4*)(ap)     : make_uint4(0,0,0,0);
            aRaw[1] = aok ? *(const uint4*)(ap + 8) : make_uint4(0,0,0,0);
            #pragma unroll
            for (int i = 0; i < 4; i++) {
                int idx = tid + i * 256;
                int r   = idx >> 5;
                int c   = (idx & 31) << 2;
                bReg[i] = __ldg((const uint4*)(Wt + (size_t)(k0 + r) * D + c));
            }
        }

        #pragma unroll
        for (int ks = 0; ks < 32; ks += 8) {
            uint32_t a[2][4];
            #pragma unroll
            for (int mt = 0; mt < 2; mt++) {
                int r0 = mBase + mt * 16 + g;
                int r1 = r0 + 8;
                a[mt][0] = As[r0][ks + t];
                a[mt][1] = As[r1][ks + t];
                a[mt][2] = As[r0][ks + t + 4];
                a[mt][3] = As[r1][ks + t + 4];
            }
            #pragma unroll
            for (int nt = 0; nt < 8; nt++) {
                int col = nBase + nt * 8 + g;
                uint32_t b0 = Bs[ks + t][col];
                uint32_t b1 = Bs[ks + t + 4][col];
                #pragma unroll
                for (int mt = 0; mt < 2; mt++)
                    mma_tf32(acc[mt][nt], a[mt][0], a[mt][1], a[mt][2], a[mt][3], b0, b1);
            }
        }
        __syncthreads();
    }

    // epilogue: scale by dinv[row], convert to fp16, write hs_h
    #pragma unroll
    for (int mt = 0; mt < 2; mt++) {
        int r0 = rowBase + mBase + mt * 16 + g;
        int r1 = r0 + 8;
        float d0 = (r0 < N_NODES) ? g_dinv[r0] : 0.0f;
        float d1 = (r1 < N_NODES) ? g_dinv[r1] : 0.0f;
        #pragma unroll
        for (int nt = 0; nt < 8; nt++) {
            int col = nBase + nt * 8 + 2 * t;
            if (r0 < N_NODES) {
                __half2 hv = __float22half2_rn(
                    make_float2(acc[mt][nt][0] * d0, acc[mt][nt][1] * d0));
                *(__half2*)(g_hsh + (size_t)r0 * D + col) = hv;
            }
            if (r1 < N_NODES) {
                __half2 hv = __float22half2_rn(
                    make_float2(acc[mt][nt][2] * d1, acc[mt][nt][3] * d1));
                *(__half2*)(g_hsh + (size_t)r1 * D + col) = hv;
            }
        }
    }
}

// ---------------- CSR gather: 2 warps per node, 64 features (32 x half2) per warp -----
// acc = sum over incoming edges of hs[src]; h = relu((acc + hs[n]) * dinv + b)
template<bool LAST>
__global__ void k_gather(const float* __restrict__ b, const int* __restrict__ batch) {
    int t     = blockIdx.x * blockDim.x + threadIdx.x;
    int warpI = t >> 5;
    int n     = warpI >> 1;            // node
    int half  = warpI & 1;             // which 64-feature half
    int lane  = t & 31;
    if (n >= N_NODES) return;

    int beg = __ldg(&g_rowptr[n]);
    int end = __ldg(&g_rowptr[n + 1]);
    int off = half * 32 + lane;        // half2 index within row

    float2 a0 = make_float2(0.f, 0.f);
    float2 a1 = a0, a2 = a0, a3 = a0;

    int e = beg;
    for (; e + 8 <= end; e += 8) {
        int s[8];
        #pragma unroll
        for (int i = 0; i < 8; i++) s[i] = __ldg(&g_esrc[e + i]);
        uint32_t raw[8];
        #pragma unroll
        for (int i = 0; i < 8; i++)
            raw[i] = __ldg((const uint32_t*)(g_hsh + (size_t)s[i] * D) + off);
        #pragma unroll
        for (int i = 0; i < 8; i++) {
            float2 f = __half22float2(*(__half2*)&raw[i]);
            float2& a = (i & 3) == 0 ? a0 : (i & 3) == 1 ? a1 : (i & 3) == 2 ? a2 : a3;
            a.x += f.x; a.y += f.y;
        }
    }
    for (; e + 4 <= end; e += 4) {
        int s0 = __ldg(&g_esrc[e]);
        int s1 = __ldg(&g_esrc[e + 1]);
        int s2 = __ldg(&g_esrc[e + 2]);
        int s3 = __ldg(&g_esrc[e + 3]);
        uint32_t r0 = __ldg((const uint32_t*)(g_hsh + (size_t)s0 * D) + off);
        uint32_t r1 = __ldg((const uint32_t*)(g_hsh + (size_t)s1 * D) + off);
        uint32_t r2 = __ldg((const uint32_t*)(g_hsh + (size_t)s2 * D) + off);
        uint32_t r3 = __ldg((const uint32_t*)(g_hsh + (size_t)s3 * D) + off);
        float2 f0 = __half22float2(*(__half2*)&r0);
        float2 f1 = __half22float2(*(__half2*)&r1);
        float2 f2 = __half22float2(*(__half2*)&r2);
        float2 f3 = __half22float2(*(__half2*)&r3);
        a0.x += f0.x; a0.y += f0.y;
        a1.x += f1.x; a1.y += f1.y;
        a2.x += f2.x; a2.y += f2.y;
        a3.x += f3.x; a3.y += f3.y;
    }
    for (; e < end; e++) {
        int s = __ldg(&g_esrc[e]);
        uint32_t r = __ldg((const uint32_t*)(g_hsh + (size_t)s * D) + off);
        float2 f = __half22float2(*(__half2*)&r);
        a0.x += f.x; a0.y += f.y;
    }

    // self-loop term + combine partials
    uint32_t sr = *((const uint32_t*)(g_hsh + (size_t)n * D) + off);
    float2 self = __half22float2(*(__half2*)&sr);
    float2 acc;
    acc.x = (a0.x + a1.x) + (a2.x + a3.x) + self.x;
    acc.y = (a0.y + a1.y) + (a2.y + a3.y) + self.y;

    float  di = g_dinv[n];
    float2 bb = __ldg((const float2*)b + off);
    float2 o;
    o.x = fmaxf(fmaf(acc.x, di, bb.x), 0.0f);
    o.y = fmaxf(fmaf(acc.y, di, bb.y), 0.0f);

    if (LAST) {
        int bg = __ldg(batch + n);
        int* q = (int*)(g_gmax + (size_t)bg * D) + off * 2;
        atomicMax(q + 0, __float_as_int(o.x));
        atomicMax(q + 1, __float_as_int(o.y));
    } else {
        __half2 hv = __float22half2_rn(o);
        ((uint32_t*)(g_hh + (size_t)n * D))[off] = *(uint32_t*)&hv;
    }
}

// ---------------- final readout ----------------
__global__ void k_final(const float* __restrict__ Wf, const float* __restrict__ bf,
                        float* __restrict__ out) {
    int t    = blockIdx.x * blockDim.x + threadIdx.x;
    int g    = t >> 5;
    int lane = t & 31;
    if (g >= N_GRAPHS) return;
    float4 v = *((const float4*)(g_gmax + (size_t)g * D) + lane);
    float4 w = __ldg((const float4*)Wf + lane);
    float s = v.x * w.x + v.y * w.y + v.z * w.z + v.w * w.w;
    #pragma unroll
    for (int o = 16; o; o >>= 1) s += __shfl_xor_sync(0xFFFFFFFFu, s, o);
    if (lane == 0) out[g] = s + bf[0];
}

// ---------------- launch: CSR build forked onto a side stream ----------------
extern "C" void kernel_launch(void* const* d_in, const int* in_sizes, int n_in,
                              void* d_out, int out_size) {
    const int*   x     = (const int*)  d_in[0];
    const int*   ei    = (const int*)  d_in[1];
    const int*   batch = (const int*)  d_in[2];
    const float* emb   = (const float*)d_in[3];
    const float* W0    = (const float*)d_in[4];
    const float* W1    = (const float*)d_in[6];
    const float* W2    = (const float*)d_in[8];
    const float* bs[3] = {(const float*)d_in[5], (const float*)d_in[7], (const float*)d_in[9]};
    const float* Wf    = (const float*)d_in[10];
    const float* bf    = (const float*)d_in[11];
    float* out = (float*)d_out;

    const int* src = ei;
    const int* dst = ei + N_EDGES;

    // persistent side stream + events (created once, before any capture)
    static cudaStream_t s2 = [] {
        cudaStream_t s; cudaStreamCreateWithFlags(&s, cudaStreamNonBlocking); return s;
    }();
    static cudaEvent_t evFork = [] {
        cudaEvent_t e; cudaEventCreateWithFlags(&e, cudaEventDisableTiming); return e;
    }();
    static cudaEvent_t evDinv = [] {
        cudaEvent_t e; cudaEventCreateWithFlags(&e, cudaEventDisableTiming); return e;
    }();
    static cudaEvent_t evCsr = [] {
        cudaEvent_t e; cudaEventCreateWithFlags(&e, cudaEventDisableTiming); return e;
    }();

    void* degPtr  = nullptr; cudaGetSymbolAddress(&degPtr,  g_deg);
    void* gmaxPtr = nullptr; cudaGetSymbolAddress(&gmaxPtr, g_gmax);

    // fork side stream off the main (capture) stream
    cudaEventRecord(evFork, 0);
    cudaStreamWaitEvent(s2, evFork, 0);

    // side stream: CSR build chain
    cudaMemsetAsync(degPtr, 0, (size_t)N_NODES * sizeof(int), s2);
    k_count_deg<<<(N_EDGES + 255) / 256, 256, 0, s2>>>(dst);
    k_blocksum<<<NBLK, 1024, 0, s2>>>();
    k_scan_part<<<1, 128, 0, s2>>>();
    k_write_csr<<<NBLK, 1024, 0, s2>>>();
    cudaEventRecord(evDinv, s2);                 // dinv + rowptr + cursor ready
    k_fill_csr<<<(N_EDGES + 255) / 256, 256, 0, s2>>>(src, dst);
    cudaEventRecord(evCsr, s2);                  // esrc ready

    // main stream: gmax clear + W prep + embedding (independent of CSR)
    cudaMemsetAsync(gmaxPtr, 0, (size_t)N_GRAPHS * D * sizeof(float));
    k_prepW<<<(3 * D * D + 255) / 256, 256>>>(W0, W1, W2);
    k_embed<<<((size_t)N_NODES * 32 + 255) / 256, 256>>>(x, emb);

    const int gatherGrid = (int)(((size_t)N_NODES * 64 + 255) / 256);
    cudaStreamWaitEvent(0, evDinv, 0);           // gemm epilogue needs dinv
    for (int l = 0; l < 3; l++) {
        k_gemm<<<(N_NODES + 127) / 128, 256>>>(l);
        if (l == 0) cudaStreamWaitEvent(0, evCsr, 0);   // gather needs CSR
        if (l < 2) k_gather<false><<<gatherGrid, 256>>>(bs[l], batch);
        else       k_gather<true ><<<gatherGrid, 256>>>(bs[l], batch);
    }

    k_final<<<(N_GRAPHS * 32 + 255) / 256, 256>>>(Wf, bf, out);
}